// round 15
// baseline (speedup 1.0000x reference)
#include <cuda_runtime.h>
#include <cuda_bf16.h>
#include <cstdint>

// Problem constants
#define B    2
#define N    512
#define MV   512
#define DIN  256
#define H    16
#define DOUT 128
#define LN_EPS 1e-5f

__device__ float g_proj[B * N * 2 * H];            // 128 KB
__device__ float g_T[B * MV * H * DOUT];           // 8 MB

#define FMA_F32X2(d_, a_, b_, c_) \
    asm("fma.rn.f32x2 %0, %1, %2, %3;" : "=l"(d_) : "l"(a_), "l"(b_), "l"(c_))

#define DUP_F32X2(d_, f_) \
    asm("mov.b64 %0, {%1, %1};" : "=l"(d_) : "f"(f_))

#define STCS_V2U64(p_, x_, y_) \
    asm volatile("st.global.cs.v2.u64 [%0], {%1, %2};" \
                 :: "l"(p_), "l"(x_), "l"(y_) : "memory")

// ---------------------------------------------------------------------------
// k1 v2: LayerNorm + proj, partial-sum form.  Grid 256 x 256 thr.
// CTA = 4 rows (halved serial chain vs R14).  Warps 0-3: LN of row w.
// Phase B: thread (w,lane) owns i-segment w*32..+31, col lane; W_in in regs.
// ---------------------------------------------------------------------------
__global__ __launch_bounds__(256) void k1(
    const float* __restrict__ feats, const float* __restrict__ gamma,
    const float* __restrict__ beta,  const float* __restrict__ W_in,
    const float* __restrict__ b_in,  float* __restrict__ proj)
{
    __shared__ __align__(16) float xs[4][DIN];        // 4 KB
    __shared__ float partials[8][4][32];              // 4 KB [iseg][row][col]

    int t    = threadIdx.x;
    int blk  = blockIdx.x;
    int w    = t >> 5;
    int lane = t & 31;

    // ---- W_in segment to registers ----
    float wv[32];
    #pragma unroll
    for (int k = 0; k < 32; k++)
        wv[k] = W_in[(w * 32 + k) * 32 + lane];       // coalesced

    // ---- Phase A: LN, warps 0-3, one row each ----
    if (w < 4) {
        int r = blk * 4 + w;
        const float4* f4 = (const float4*)(feats + (size_t)r * DIN);
        float4 va = f4[lane * 2], vb = f4[lane * 2 + 1];
        float s  = va.x + va.y + va.z + va.w + vb.x + vb.y + vb.z + vb.w;
        float s2 = va.x*va.x + va.y*va.y + va.z*va.z + va.w*va.w
                 + vb.x*vb.x + vb.y*vb.y + vb.z*vb.z + vb.w*vb.w;
        #pragma unroll
        for (int o = 16; o; o >>= 1) {
            s  += __shfl_xor_sync(0xFFFFFFFFu, s,  o);
            s2 += __shfl_xor_sync(0xFFFFFFFFu, s2, o);
        }
        float mu  = s  * (1.f / DIN);
        float var = s2 * (1.f / DIN) - mu * mu;
        float rs  = rsqrtf(var + LN_EPS);

        const float4* g4 = (const float4*)gamma;
        const float4* b4 = (const float4*)beta;
        float4 ga = g4[lane * 2], gb = g4[lane * 2 + 1];
        float4 ba = b4[lane * 2], bb = b4[lane * 2 + 1];
        float* xrow = xs[w] + lane * 8;
        xrow[0] = (va.x - mu) * rs * ga.x + ba.x;
        xrow[1] = (va.y - mu) * rs * ga.y + ba.y;
        xrow[2] = (va.z - mu) * rs * ga.z + ba.z;
        xrow[3] = (va.w - mu) * rs * ga.w + ba.w;
        xrow[4] = (vb.x - mu) * rs * gb.x + bb.x;
        xrow[5] = (vb.y - mu) * rs * gb.y + bb.y;
        xrow[6] = (vb.z - mu) * rs * gb.z + bb.z;
        xrow[7] = (vb.w - mu) * rs * gb.w + bb.w;
    }
    __syncthreads();

    // ---- Phase B: partial sums over 4 rows ----
    #pragma unroll
    for (int rr = 0; rr < 4; rr++) {
        const float4* xr4 = (const float4*)(xs[rr] + w * 32);
        float4 x0 = xr4[0], x1 = xr4[1], x2 = xr4[2], x3 = xr4[3];
        float4 x4 = xr4[4], x5 = xr4[5], x6 = xr4[6], x7 = xr4[7];
        float xk[32] = { x0.x,x0.y,x0.z,x0.w, x1.x,x1.y,x1.z,x1.w,
                         x2.x,x2.y,x2.z,x2.w, x3.x,x3.y,x3.z,x3.w,
                         x4.x,x4.y,x4.z,x4.w, x5.x,x5.y,x5.z,x5.w,
                         x6.x,x6.y,x6.z,x6.w, x7.x,x7.y,x7.z,x7.w };
        float a0 = 0.f, a1 = 0.f, a2 = 0.f, a3 = 0.f;
        #pragma unroll
        for (int k = 0; k < 32; k += 4) {
            a0 = fmaf(xk[k],     wv[k],     a0);
            a1 = fmaf(xk[k + 1], wv[k + 1], a1);
            a2 = fmaf(xk[k + 2], wv[k + 2], a2);
            a3 = fmaf(xk[k + 3], wv[k + 3], a3);
        }
        partials[w][rr][lane] = (a0 + a1) + (a2 + a3);
    }
    __syncthreads();

    // ---- reduce across 8 i-segments; threads 0..127 write 4 rows ----
    if (t < 128) {
        int row = t >> 5, col = t & 31;
        float pv = b_in[col];
        #pragma unroll
        for (int wp = 0; wp < 8; wp++) pv += partials[wp][row][col];
        proj[(blk * 4 + row) * 32 + col] = pv;
    }
}

// ---------------------------------------------------------------------------
// k2 (R14 verbatim): T[bm][p][d] = sum_q W_out[d][p*16+q] * bq[bm][q].
// Grid 128 x 256 thr.  CTA = 16 rows x 8 p; W slice transposed in smem.
// ---------------------------------------------------------------------------
#define K2_WSTRIDE 129
#define K2_SMEM_BYTES ((128 * K2_WSTRIDE + 16 * 16) * 4)   // 67,072 B

__global__ __launch_bounds__(256) void k2(
    const float* __restrict__ proj, const float* __restrict__ W_out,
    float* __restrict__ T)
{
    extern __shared__ float sm2[];
    float* Wsl = sm2;                      // [128 pql][129]
    float* bqs = sm2 + 128 * K2_WSTRIDE;   // [16 mm][16 q]

    int t  = threadIdx.x;
    int rg = blockIdx.x >> 1;              // 0..63 -> rows rg*16..+15
    int ph = blockIdx.x & 1;               // p = ph*8 .. ph*8+7

    {
        const float4* W4 = (const float4*)W_out;       // [128 d][64 pq4]
        #pragma unroll
        for (int it = 0; it < 16; it++) {
            int idx = t + it * 256;                    // 0..4095
            int dd  = idx >> 5;                        // 0..127
            int c4  = idx & 31;                        // 0..31
            float4 v = W4[dd * 64 + ph * 32 + c4];
            int pql = c4 * 4;
            Wsl[(pql + 0) * K2_WSTRIDE + dd] = v.x;
            Wsl[(pql + 1) * K2_WSTRIDE + dd] = v.y;
            Wsl[(pql + 2) * K2_WSTRIDE + dd] = v.z;
            Wsl[(pql + 3) * K2_WSTRIDE + dd] = v.w;
        }
    }
    {
        int mm = t >> 4, q = t & 15;
        bqs[mm * 16 + q] = proj[(rg * 16 + mm) * 32 + 16 + q];
    }
    __syncthreads();

    {
        int d = t & 127;
        int h = t >> 7;                                // 0..1
        float wq[4][16];
        #pragma unroll
        for (int pi = 0; pi < 4; pi++) {
            int pl = h * 4 + pi;
            #pragma unroll
            for (int q = 0; q < 16; q++)
                wq[pi][q] = Wsl[(pl * 16 + q) * K2_WSTRIDE + d];
        }
        #pragma unroll
        for (int mm = 0; mm < 16; mm++) {
            float acc[4] = {0.f, 0.f, 0.f, 0.f};
            #pragma unroll
            for (int q = 0; q < 16; q++) {
                float bv = bqs[mm * 16 + q];
                acc[0] = fmaf(wq[0][q], bv, acc[0]);
                acc[1] = fmaf(wq[1][q], bv, acc[1]);
                acc[2] = fmaf(wq[2][q], bv, acc[2]);
                acc[3] = fmaf(wq[3][q], bv, acc[3]);
            }
            size_t bm = (size_t)(rg * 16 + mm);
            #pragma unroll
            for (int pi = 0; pi < 4; pi++) {
                int p = ph * 8 + h * 4 + pi;
                T[(bm * H + p) * DOUT + d] = acc[pi];
            }
        }
    }
}

// ---------------------------------------------------------------------------
// k_main v8: R7 structure, occupancy 3 attempt (ptxas target <=85 regs).
// Grid 1024, 256 thr.  CTA = one (b,m), warp = 64 rows, T in 32 reg-pairs.
// ---------------------------------------------------------------------------
__global__ __launch_bounds__(256, 3) void k_main(
    const float* __restrict__ proj, const float* __restrict__ Tg,
    const float* __restrict__ b_out, float* __restrict__ out)
{
    int b    = blockIdx.x >> 9;
    int m    = blockIdx.x & 511;
    int t    = threadIdx.x;
    int w    = t >> 5;              // warp -> rows w*64 .. w*64+63
    int lane = t & 31;              // chunk: d = lane*4 .. +3

    __shared__ __align__(16) float Ts[H * DOUT];   // 8 KB  [p][d]
    __shared__ __align__(16) float As[N * H];      // 32 KB [row][p]

    {
        const float4* Tsrc = (const float4*)(Tg + (size_t)(b * N + m) * (H * DOUT));
        float4* Td = (float4*)Ts;
        Td[t]       = Tsrc[t];
        Td[t + 256] = Tsrc[t + 256];
    }
    {
        const float4* psrc = (const float4*)(proj + (size_t)b * N * 32);
        float4* Ad = (float4*)As;
        #pragma unroll
        for (int it = 0; it < 8; it++) {
            int idx = t + it * 256;
            int row = idx >> 2;
            int q4  = idx & 3;
            Ad[idx] = psrc[row * 8 + q4];
        }
    }
    __syncthreads();

    unsigned long long Tp[H][2];
    {
        const ulonglong2* TU = (const ulonglong2*)Ts;
        #pragma unroll
        for (int p = 0; p < H; p++) {
            ulonglong2 q = TU[p * 32 + lane];
            Tp[p][0] = q.x; Tp[p][1] = q.y;
        }
    }

    unsigned long long bo0, bo1;
    {
        const unsigned long long* bo = (const unsigned long long*)b_out;
        bo0 = bo[2 * lane]; bo1 = bo[2 * lane + 1];
    }

    size_t rowstride = (size_t)MV * DOUT;
    float* obase = out + (((size_t)(b * N) + w * 64) * MV + m) * DOUT + lane * 4;

    #pragma unroll 1
    for (int jb = 0; jb < 64; jb += 4) {
        unsigned long long acc[4][2];
        #pragma unroll
        for (int j = 0; j < 4; j++) { acc[j][0] = bo0; acc[j][1] = bo1; }

        #pragma unroll
        for (int j = 0; j < 4; j++) {
            int row = w * 64 + jb + j;
            const float4* ar = (const float4*)(As + row * H);
            float4 A0 = ar[0], A1 = ar[1], A2 = ar[2], A3 = ar[3];
            unsigned long long ad;
            DUP_F32X2(ad, A0.x); FMA_F32X2(acc[j][0], ad, Tp[0][0], acc[j][0]); FMA_F32X2(acc[j][1], ad, Tp[0][1], acc[j][1]);
            DUP_F32X2(ad, A0.y); FMA_F32X2(acc[j][0], ad, Tp[1][0], acc[j][0]); FMA_F32X2(acc[j][1], ad, Tp[1][1], acc[j][1]);
            DUP_F32X2(ad, A0.z); FMA_F32X2(acc[j][0], ad, Tp[2][0], acc[j][0]); FMA_F32X2(acc[j][1], ad, Tp[2][1], acc[j][1]);
            DUP_F32X2(ad, A0.w); FMA_F32X2(acc[j][0], ad, Tp[3][0], acc[j][0]); FMA_F32X2(acc[j][1], ad, Tp[3][1], acc[j][1]);
            DUP_F32X2(ad, A1.x); FMA_F32X2(acc[j][0], ad, Tp[4][0], acc[j][0]); FMA_F32X2(acc[j][1], ad, Tp[4][1], acc[j][1]);
            DUP_F32X2(ad, A1.y); FMA_F32X2(acc[j][0], ad, Tp[5][0], acc[j][0]); FMA_F32X2(acc[j][1], ad, Tp[5][1], acc[j][1]);
            DUP_F32X2(ad, A1.z); FMA_F32X2(acc[j][0], ad, Tp[6][0], acc[j][0]); FMA_F32X2(acc[j][1], ad, Tp[6][1], acc[j][1]);
            DUP_F32X2(ad, A1.w); FMA_F32X2(acc[j][0], ad, Tp[7][0], acc[j][0]); FMA_F32X2(acc[j][1], ad, Tp[7][1], acc[j][1]);
            DUP_F32X2(ad, A2.x); FMA_F32X2(acc[j][0], ad, Tp[8][0], acc[j][0]); FMA_F32X2(acc[j][1], ad, Tp[8][1], acc[j][1]);
            DUP_F32X2(ad, A2.y); FMA_F32X2(acc[j][0], ad, Tp[9][0], acc[j][0]); FMA_F32X2(acc[j][1], ad, Tp[9][1], acc[j][1]);
            DUP_F32X2(ad, A2.z); FMA_F32X2(acc[j][0], ad, Tp[10][0], acc[j][0]); FMA_F32X2(acc[j][1], ad, Tp[10][1], acc[j][1]);
            DUP_F32X2(ad, A2.w); FMA_F32X2(acc[j][0], ad, Tp[11][0], acc[j][0]); FMA_F32X2(acc[j][1], ad, Tp[11][1], acc[j][1]);
            DUP_F32X2(ad, A3.x); FMA_F32X2(acc[j][0], ad, Tp[12][0], acc[j][0]); FMA_F32X2(acc[j][1], ad, Tp[12][1], acc[j][1]);
            DUP_F32X2(ad, A3.y); FMA_F32X2(acc[j][0], ad, Tp[13][0], acc[j][0]); FMA_F32X2(acc[j][1], ad, Tp[13][1], acc[j][1]);
            DUP_F32X2(ad, A3.z); FMA_F32X2(acc[j][0], ad, Tp[14][0], acc[j][0]); FMA_F32X2(acc[j][1], ad, Tp[14][1], acc[j][1]);
            DUP_F32X2(ad, A3.w); FMA_F32X2(acc[j][0], ad, Tp[15][0], acc[j][0]); FMA_F32X2(acc[j][1], ad, Tp[15][1], acc[j][1]);
        }

        float* op = obase + (size_t)jb * rowstride;
        #pragma unroll
        for (int j = 0; j < 4; j++)
            STCS_V2U64(op + (size_t)j * rowstride, acc[j][0], acc[j][1]);
    }
}

// ---------------------------------------------------------------------------
extern "C" void kernel_launch(void* const* d_in, const int* in_sizes, int n_in,
                              void* d_out, int out_size)
{
    const float* feats  = (const float*)d_in[0];
    const float* gamma  = (const float*)d_in[1];
    const float* beta   = (const float*)d_in[2];
    const float* W_in   = (const float*)d_in[3];
    const float* b_in   = (const float*)d_in[4];
    const float* W_out  = (const float*)d_in[5];
    const float* b_out  = (const float*)d_in[6];
    float* out = (float*)d_out;

    float* proj; cudaGetSymbolAddress((void**)&proj, g_proj);
    float* T;    cudaGetSymbolAddress((void**)&T,    g_T);

    cudaFuncSetAttribute(k2, cudaFuncAttributeMaxDynamicSharedMemorySize,
                         K2_SMEM_BYTES);

    k1<<<(B * N) / 4, 256>>>(feats, gamma, beta, W_in, b_in, proj);
    k2<<<128, 256, K2_SMEM_BYTES>>>(proj, W_out, T);
    k_main<<<B * MV, 256>>>(proj, T, b_out, out);
}

// round 16
// speedup vs baseline: 1.0575x; 1.0575x over previous
#include <cuda_runtime.h>
#include <cuda_bf16.h>
#include <cstdint>

// Problem constants
#define B    2
#define N    512
#define MV   512
#define DIN  256
#define H    16
#define DOUT 128
#define LN_EPS 1e-5f

__device__ float g_proj[B * N * 2 * H];            // 128 KB
__device__ float g_T[B * MV * H * DOUT];           // 8 MB

#define FMA_F32X2(d_, a_, b_, c_) \
    asm("fma.rn.f32x2 %0, %1, %2, %3;" : "=l"(d_) : "l"(a_), "l"(b_), "l"(c_))

#define DUP_F32X2(d_, f_) \
    asm("mov.b64 %0, {%1, %1};" : "=l"(d_) : "f"(f_))

#define STCS_V2U64(p_, x_, y_) \
    asm volatile("st.global.cs.v2.u64 [%0], {%1, %2};" \
                 :: "l"(p_), "l"(x_), "l"(y_) : "memory")

// ---------------------------------------------------------------------------
// k1 v3: LayerNorm + proj.  Grid 128 x 512 thr (16 warps).
// CTA = 8 rows.  Warp w owns i-segment w*16..w*16+15 (wv[16] in regs).
// Warps 0-7 additionally do LN of row w.  16 warps hide the per-CTA
// W_in / feats load latency that dominated the 256-thread version.
// ---------------------------------------------------------------------------
__global__ __launch_bounds__(512) void k1(
    const float* __restrict__ feats, const float* __restrict__ gamma,
    const float* __restrict__ beta,  const float* __restrict__ W_in,
    const float* __restrict__ b_in,  float* __restrict__ proj)
{
    __shared__ __align__(16) float xs[8][DIN];        // 8 KB
    __shared__ float partials[16][8][32];             // 16 KB [iseg][row][col]

    int t    = threadIdx.x;
    int blk  = blockIdx.x;
    int w    = t >> 5;               // 0..15
    int lane = t & 31;

    // ---- W_in segment to registers: wv[k] = W_in[(w*16+k)*32 + lane] ----
    float wv[16];
    #pragma unroll
    for (int k = 0; k < 16; k++)
        wv[k] = W_in[(w * 16 + k) * 32 + lane];       // coalesced

    // ---- Phase A: LN, warps 0-7, one row each ----
    if (w < 8) {
        int r = blk * 8 + w;
        const float4* f4 = (const float4*)(feats + (size_t)r * DIN);
        float4 va = f4[lane * 2], vb = f4[lane * 2 + 1];
        float s  = va.x + va.y + va.z + va.w + vb.x + vb.y + vb.z + vb.w;
        float s2 = va.x*va.x + va.y*va.y + va.z*va.z + va.w*va.w
                 + vb.x*vb.x + vb.y*vb.y + vb.z*vb.z + vb.w*vb.w;
        #pragma unroll
        for (int o = 16; o; o >>= 1) {
            s  += __shfl_xor_sync(0xFFFFFFFFu, s,  o);
            s2 += __shfl_xor_sync(0xFFFFFFFFu, s2, o);
        }
        float mu  = s  * (1.f / DIN);
        float var = s2 * (1.f / DIN) - mu * mu;
        float rs  = rsqrtf(var + LN_EPS);

        const float4* g4 = (const float4*)gamma;
        const float4* b4 = (const float4*)beta;
        float4 ga = g4[lane * 2], gb = g4[lane * 2 + 1];
        float4 ba = b4[lane * 2], bb = b4[lane * 2 + 1];
        float* xrow = xs[w] + lane * 8;
        xrow[0] = (va.x - mu) * rs * ga.x + ba.x;
        xrow[1] = (va.y - mu) * rs * ga.y + ba.y;
        xrow[2] = (va.z - mu) * rs * ga.z + ba.z;
        xrow[3] = (va.w - mu) * rs * ga.w + ba.w;
        xrow[4] = (vb.x - mu) * rs * gb.x + bb.x;
        xrow[5] = (vb.y - mu) * rs * gb.y + bb.y;
        xrow[6] = (vb.z - mu) * rs * gb.z + bb.z;
        xrow[7] = (vb.w - mu) * rs * gb.w + bb.w;
    }
    __syncthreads();

    // ---- Phase B: partial sums, 8 rows x 16 FMA each ----
    #pragma unroll
    for (int rr = 0; rr < 8; rr++) {
        const float4* xr4 = (const float4*)(xs[rr] + w * 16);
        float4 x0 = xr4[0], x1 = xr4[1], x2 = xr4[2], x3 = xr4[3];
        float xk[16] = { x0.x,x0.y,x0.z,x0.w, x1.x,x1.y,x1.z,x1.w,
                         x2.x,x2.y,x2.z,x2.w, x3.x,x3.y,x3.z,x3.w };
        float a0 = 0.f, a1 = 0.f, a2 = 0.f, a3 = 0.f;
        #pragma unroll
        for (int k = 0; k < 16; k += 4) {
            a0 = fmaf(xk[k],     wv[k],     a0);
            a1 = fmaf(xk[k + 1], wv[k + 1], a1);
            a2 = fmaf(xk[k + 2], wv[k + 2], a2);
            a3 = fmaf(xk[k + 3], wv[k + 3], a3);
        }
        partials[w][rr][lane] = (a0 + a1) + (a2 + a3);
    }
    __syncthreads();

    // ---- reduce across 16 i-segments; threads 0..255 write 8 rows ----
    if (t < 256) {
        int row = t >> 5, col = t & 31;
        float pv = b_in[col];
        #pragma unroll
        for (int wp = 0; wp < 16; wp++) pv += partials[wp][row][col];
        proj[(blk * 8 + row) * 32 + col] = pv;
    }
}

// ---------------------------------------------------------------------------
// k2 (R14 verbatim): T[bm][p][d] = sum_q W_out[d][p*16+q] * bq[bm][q].
// Grid 128 x 256 thr.  CTA = 16 rows x 8 p; W slice transposed in smem.
// ---------------------------------------------------------------------------
#define K2_WSTRIDE 129
#define K2_SMEM_BYTES ((128 * K2_WSTRIDE + 16 * 16) * 4)   // 67,072 B

__global__ __launch_bounds__(256) void k2(
    const float* __restrict__ proj, const float* __restrict__ W_out,
    float* __restrict__ T)
{
    extern __shared__ float sm2[];
    float* Wsl = sm2;                      // [128 pql][129]
    float* bqs = sm2 + 128 * K2_WSTRIDE;   // [16 mm][16 q]

    int t  = threadIdx.x;
    int rg = blockIdx.x >> 1;              // 0..63 -> rows rg*16..+15
    int ph = blockIdx.x & 1;               // p = ph*8 .. ph*8+7

    {
        const float4* W4 = (const float4*)W_out;       // [128 d][64 pq4]
        #pragma unroll
        for (int it = 0; it < 16; it++) {
            int idx = t + it * 256;                    // 0..4095
            int dd  = idx >> 5;                        // 0..127
            int c4  = idx & 31;                        // 0..31
            float4 v = W4[dd * 64 + ph * 32 + c4];
            int pql = c4 * 4;
            Wsl[(pql + 0) * K2_WSTRIDE + dd] = v.x;
            Wsl[(pql + 1) * K2_WSTRIDE + dd] = v.y;
            Wsl[(pql + 2) * K2_WSTRIDE + dd] = v.z;
            Wsl[(pql + 3) * K2_WSTRIDE + dd] = v.w;
        }
    }
    {
        int mm = t >> 4, q = t & 15;
        bqs[mm * 16 + q] = proj[(rg * 16 + mm) * 32 + 16 + q];
    }
    __syncthreads();

    {
        int d = t & 127;
        int h = t >> 7;                                // 0..1
        float wq[4][16];
        #pragma unroll
        for (int pi = 0; pi < 4; pi++) {
            int pl = h * 4 + pi;
            #pragma unroll
            for (int q = 0; q < 16; q++)
                wq[pi][q] = Wsl[(pl * 16 + q) * K2_WSTRIDE + d];
        }
        #pragma unroll
        for (int mm = 0; mm < 16; mm++) {
            float acc[4] = {0.f, 0.f, 0.f, 0.f};
            #pragma unroll
            for (int q = 0; q < 16; q++) {
                float bv = bqs[mm * 16 + q];
                acc[0] = fmaf(wq[0][q], bv, acc[0]);
                acc[1] = fmaf(wq[1][q], bv, acc[1]);
                acc[2] = fmaf(wq[2][q], bv, acc[2]);
                acc[3] = fmaf(wq[3][q], bv, acc[3]);
            }
            size_t bm = (size_t)(rg * 16 + mm);
            #pragma unroll
            for (int pi = 0; pi < 4; pi++) {
                int p = ph * 8 + h * 4 + pi;
                T[(bm * H + p) * DOUT + d] = acc[pi];
            }
        }
    }
}

// ---------------------------------------------------------------------------
// k_main (R7 verbatim, FROZEN): out = b_out + sum_p a * T
// Grid 1024, 256 thr, occ 2.  CTA = one (b,m); warp = 64 rows; T in regs.
// ---------------------------------------------------------------------------
__global__ __launch_bounds__(256, 2) void k_main(
    const float* __restrict__ proj, const float* __restrict__ Tg,
    const float* __restrict__ b_out, float* __restrict__ out)
{
    int b    = blockIdx.x >> 9;
    int m    = blockIdx.x & 511;
    int t    = threadIdx.x;
    int w    = t >> 5;              // warp -> rows w*64 .. w*64+63
    int lane = t & 31;              // chunk: d = lane*4 .. +3

    __shared__ __align__(16) float Ts[H * DOUT];   // 8 KB  [p][d]
    __shared__ __align__(16) float As[N * H];      // 32 KB [row][p]

    {
        const float4* Tsrc = (const float4*)(Tg + (size_t)(b * N + m) * (H * DOUT));
        float4* Td = (float4*)Ts;
        Td[t]       = Tsrc[t];
        Td[t + 256] = Tsrc[t + 256];
    }
    {
        const float4* psrc = (const float4*)(proj + (size_t)b * N * 32);
        float4* Ad = (float4*)As;
        #pragma unroll
        for (int it = 0; it < 8; it++) {
            int idx = t + it * 256;
            int row = idx >> 2;
            int q4  = idx & 3;
            Ad[idx] = psrc[row * 8 + q4];
        }
    }
    __syncthreads();

    unsigned long long Tp[H][2];
    {
        const ulonglong2* TU = (const ulonglong2*)Ts;
        #pragma unroll
        for (int p = 0; p < H; p++) {
            ulonglong2 q = TU[p * 32 + lane];
            Tp[p][0] = q.x; Tp[p][1] = q.y;
        }
    }

    unsigned long long bo0, bo1;
    {
        const unsigned long long* bo = (const unsigned long long*)b_out;
        bo0 = bo[2 * lane]; bo1 = bo[2 * lane + 1];
    }

    size_t rowstride = (size_t)MV * DOUT;
    float* obase = out + (((size_t)(b * N) + w * 64) * MV + m) * DOUT + lane * 4;

    #pragma unroll 1
    for (int jb = 0; jb < 64; jb += 4) {
        unsigned long long acc[4][2];
        #pragma unroll
        for (int j = 0; j < 4; j++) { acc[j][0] = bo0; acc[j][1] = bo1; }

        #pragma unroll
        for (int j = 0; j < 4; j++) {
            int row = w * 64 + jb + j;
            const float4* ar = (const float4*)(As + row * H);
            float4 A0 = ar[0], A1 = ar[1], A2 = ar[2], A3 = ar[3];
            float a16[16] = { A0.x,A0.y,A0.z,A0.w, A1.x,A1.y,A1.z,A1.w,
                              A2.x,A2.y,A2.z,A2.w, A3.x,A3.y,A3.z,A3.w };
            #pragma unroll
            for (int p = 0; p < H; p++) {
                unsigned long long ad;
                DUP_F32X2(ad, a16[p]);
                FMA_F32X2(acc[j][0], ad, Tp[p][0], acc[j][0]);
                FMA_F32X2(acc[j][1], ad, Tp[p][1], acc[j][1]);
            }
        }

        float* op = obase + (size_t)jb * rowstride;
        #pragma unroll
        for (int j = 0; j < 4; j++)
            STCS_V2U64(op + (size_t)j * rowstride, acc[j][0], acc[j][1]);
    }
}

// ---------------------------------------------------------------------------
extern "C" void kernel_launch(void* const* d_in, const int* in_sizes, int n_in,
                              void* d_out, int out_size)
{
    const float* feats  = (const float*)d_in[0];
    const float* gamma  = (const float*)d_in[1];
    const float* beta   = (const float*)d_in[2];
    const float* W_in   = (const float*)d_in[3];
    const float* b_in   = (const float*)d_in[4];
    const float* W_out  = (const float*)d_in[5];
    const float* b_out  = (const float*)d_in[6];
    float* out = (float*)d_out;

    float* proj; cudaGetSymbolAddress((void**)&proj, g_proj);
    float* T;    cudaGetSymbolAddress((void**)&T,    g_T);

    cudaFuncSetAttribute(k2, cudaFuncAttributeMaxDynamicSharedMemorySize,
                         K2_SMEM_BYTES);

    k1<<<(B * N) / 8, 512>>>(feats, gamma, beta, W_in, b_in, proj);
    k2<<<128, 256, K2_SMEM_BYTES>>>(proj, W_out, T);
    k_main<<<B * MV, 256>>>(proj, T, b_out, out);
}